// round 4
// baseline (speedup 1.0000x reference)
#include <cuda_runtime.h>

#define N_NODES 1048576
#define N_EDGES (4 * N_NODES)

typedef unsigned long long u64;

// Scratch: per-node (sum0,sum1,sum2,count) + padded x. 32 MB device globals.
__device__ float4 g_scr[N_NODES];
__device__ float4 g_x4[N_NODES];

__device__ __forceinline__ u64 fma2(u64 a, u64 b, u64 c) {
    u64 d;
    asm("fma.rn.f32x2 %0, %1, %2, %3;" : "=l"(d) : "l"(a), "l"(b), "l"(c));
    return d;
}
__device__ __forceinline__ u64 pack2(float lo, float hi) {
    u64 d;
    asm("mov.b64 %0, {%1, %2};" : "=l"(d) : "f"(lo), "f"(hi));
    return d;
}
__device__ __forceinline__ void unpack2(u64 a, float& lo, float& hi) {
    asm("mov.b64 {%0, %1}, %2;" : "=f"(lo), "=f"(hi) : "l"(a));
}
__device__ __forceinline__ u64 relu2(u64 a) {
    float lo, hi;
    unpack2(a, lo, hi);
    return pack2(fmaxf(lo, 0.f), fmaxf(hi, 0.f));
}

// Evict-last policy (per-thread, cheap).
__device__ __forceinline__ u64 mk_policy_last() {
    u64 pol;
    asm("createpolicy.fractional.L2::evict_last.b64 %0, 1.0;" : "=l"(pol));
    return pol;
}

// L2-resident gather: keep x table pinned in L2 via cache-hint policy.
__device__ __forceinline__ float4 ldg_resident(const float4* p, u64 pol) {
    float4 v;
    asm volatile("ld.global.nc.L2::cache_hint.v4.f32 {%0,%1,%2,%3}, [%4], %5;"
                 : "=f"(v.x), "=f"(v.y), "=f"(v.z), "=f"(v.w) : "l"(p), "l"(pol));
    return v;
}
// Streaming loads: evict-first so streams don't pollute L2.
__device__ __forceinline__ int2 ldg_stream_i2(const int* p) {
    int2 v;
    asm volatile("ld.global.cs.v2.b32 {%0,%1}, [%2];" : "=r"(v.x), "=r"(v.y) : "l"(p));
    return v;
}
__device__ __forceinline__ float2 ldg_stream_f2(const float* p) {
    float2 v;
    asm volatile("ld.global.cs.v2.f32 {%0,%1}, [%2];" : "=f"(v.x), "=f"(v.y) : "l"(p));
    return v;
}
__device__ __forceinline__ void st_resident(float4* p, float4 v, u64 pol) {
    asm volatile("st.global.L2::cache_hint.v4.f32 [%0], {%1,%2,%3,%4}, %5;"
                 :: "l"(p), "f"(v.x), "f"(v.y), "f"(v.z), "f"(v.w), "l"(pol) : "memory");
}

// Zero scratch + pad x[N,3] into float4 table. 4 nodes per thread, vectorized.
__global__ void __launch_bounds__(256) prep_kernel(const float4* __restrict__ x) {
    int i = blockIdx.x * blockDim.x + threadIdx.x;   // group of 4 nodes
    if (i >= N_NODES / 4) return;
    u64 pol = mk_policy_last();
    // 4 nodes = 12 floats = 3 float4
    float4 a = x[3 * i];
    float4 b = x[3 * i + 1];
    float4 c = x[3 * i + 2];
    int n = 4 * i;
    st_resident(&g_x4[n],     make_float4(a.x, a.y, a.z, 0.f), pol);
    st_resident(&g_x4[n + 1], make_float4(a.w, b.x, b.y, 0.f), pol);
    st_resident(&g_x4[n + 2], make_float4(b.z, b.w, c.x, 0.f), pol);
    st_resident(&g_x4[n + 3], make_float4(c.y, c.z, c.w, 0.f), pol);
    float4 z = make_float4(0.f, 0.f, 0.f, 0.f);
    st_resident(&g_scr[n],     z, pol);
    st_resident(&g_scr[n + 1], z, pol);
    st_resident(&g_scr[n + 2], z, pol);
    st_resident(&g_scr[n + 3], z, pol);
}

// Edge MLP + scatter-add. TWO edges per thread, packed f32x2 math.
__global__ void __launch_bounds__(256) edge_kernel(
        const int*   __restrict__ ei,
        const float* __restrict__ eattr,
        const float* __restrict__ w1a,
        const float* __restrict__ b1a,
        const float* __restrict__ w1b,
        const float* __restrict__ b1b) {
    // per hidden j: [wx, wy, wz, ww, bias, v0, v1, v2], each scalar duplicated.
    __shared__ __align__(16) u64 sw[20][8];
    int t = threadIdx.x;
    if (t < 20) {
        sw[t][0] = pack2(w1a[t],          w1a[t]);
        sw[t][1] = pack2(w1a[20 + t],     w1a[20 + t]);
        sw[t][2] = pack2(w1a[40 + t],     w1a[40 + t]);
        sw[t][3] = pack2(w1a[60 + t],     w1a[60 + t]);
        sw[t][4] = pack2(b1a[t],          b1a[t]);
        sw[t][5] = pack2(w1b[3 * t],      w1b[3 * t]);
        sw[t][6] = pack2(w1b[3 * t + 1],  w1b[3 * t + 1]);
        sw[t][7] = pack2(w1b[3 * t + 2],  w1b[3 * t + 2]);
    }
    __syncthreads();

    int e = (blockIdx.x * 256 + t) * 2;
    if (e >= N_EDGES) return;

    u64 pol = mk_policy_last();

    int2   rr = ldg_stream_i2(ei + e);             // source nodes
    int2   cc = ldg_stream_i2(ei + N_EDGES + e);   // destination nodes
    float2 ef = ldg_stream_f2(eattr + e);

    float4 xa = ldg_resident(&g_x4[rr.x], pol);
    float4 xb = ldg_resident(&g_x4[rr.y], pol);

    u64 X0 = pack2(xa.x, xb.x);
    u64 X1 = pack2(xa.y, xb.y);
    u64 X2 = pack2(xa.z, xb.z);
    u64 EA = pack2(ef.x, ef.y);

    float bb0 = b1b[0], bb1 = b1b[1], bb2 = b1b[2];
    u64 o0 = pack2(bb0, bb0);
    u64 o1 = pack2(bb1, bb1);
    u64 o2 = pack2(bb2, bb2);

#pragma unroll
    for (int j = 0; j < 20; j++) {
        const u64* w = sw[j];
        u64 h = fma2(X0, w[0], fma2(X1, w[1], fma2(X2, w[2], fma2(EA, w[3], w[4]))));
        h = relu2(h);
        o0 = fma2(h, w[5], o0);
        o1 = fma2(h, w[6], o1);
        o2 = fma2(h, w[7], o2);
    }

    float a0, b0, a1, b1v, a2, b2v;
    unpack2(o0, a0, b0);
    unpack2(o1, a1, b1v);
    unpack2(o2, a2, b2v);

    asm volatile("red.global.add.v4.f32 [%0], {%1, %2, %3, %4};"
                 :: "l"(g_scr + cc.x), "f"(a0), "f"(a1), "f"(a2), "f"(1.0f) : "memory");
    asm volatile("red.global.add.v4.f32 [%0], {%1, %2, %3, %4};"
                 :: "l"(g_scr + cc.y), "f"(b0), "f"(b1v), "f"(b2v), "f"(1.0f) : "memory");
}

// Node MLP + L2 normalize. TWO nodes per thread, packed f32x2 math.
__global__ void __launch_bounds__(256) node_kernel(
        const float* __restrict__ w2a,
        const float* __restrict__ b2a,
        const float* __restrict__ w2b,
        const float* __restrict__ b2b,
        float* __restrict__ out) {
    // per hidden j: [w0..w5, bias, v0, v1, v2], duplicated. Row = 80B (16B-aligned).
    __shared__ __align__(16) u64 sw[20][10];
    int t = threadIdx.x;
    if (t < 20) {
        sw[t][0] = pack2(w2a[t],           w2a[t]);
        sw[t][1] = pack2(w2a[20 + t],      w2a[20 + t]);
        sw[t][2] = pack2(w2a[40 + t],      w2a[40 + t]);
        sw[t][3] = pack2(w2a[60 + t],      w2a[60 + t]);
        sw[t][4] = pack2(w2a[80 + t],      w2a[80 + t]);
        sw[t][5] = pack2(w2a[100 + t],     w2a[100 + t]);
        sw[t][6] = pack2(b2a[t],           b2a[t]);
        sw[t][7] = pack2(w2b[3 * t],       w2b[3 * t]);
        sw[t][8] = pack2(w2b[3 * t + 1],   w2b[3 * t + 1]);
        sw[t][9] = pack2(w2b[3 * t + 2],   w2b[3 * t + 2]);
    }
    __syncthreads();

    int i = (blockIdx.x * 256 + t) * 2;
    if (i >= N_NODES) return;

    float4 sA = g_scr[i];
    float4 sB = g_scr[i + 1];
    float4 xA = g_x4[i];
    float4 xB = g_x4[i + 1];

    float invA = 1.0f / fmaxf(sA.w, 1.0f);
    float invB = 1.0f / fmaxf(sB.w, 1.0f);

    u64 X0 = pack2(xA.x, xB.x);
    u64 X1 = pack2(xA.y, xB.y);
    u64 X2 = pack2(xA.z, xB.z);
    u64 A0 = pack2(sA.x * invA, sB.x * invB);
    u64 A1 = pack2(sA.y * invA, sB.y * invB);
    u64 A2 = pack2(sA.z * invA, sB.z * invB);

    float bb0 = b2b[0], bb1 = b2b[1], bb2 = b2b[2];
    u64 o0 = pack2(bb0, bb0);
    u64 o1 = pack2(bb1, bb1);
    u64 o2 = pack2(bb2, bb2);

#pragma unroll
    for (int j = 0; j < 20; j++) {
        const u64* w = sw[j];
        u64 h = fma2(X0, w[0],
                fma2(X1, w[1],
                fma2(X2, w[2],
                fma2(A0, w[3],
                fma2(A1, w[4],
                fma2(A2, w[5], w[6]))))));
        h = relu2(h);
        o0 = fma2(h, w[7], o0);
        o1 = fma2(h, w[8], o1);
        o2 = fma2(h, w[9], o2);
    }

    float pA0, pB0, pA1, pB1, pA2, pB2;
    unpack2(o0, pA0, pB0);
    unpack2(o1, pA1, pB1);
    unpack2(o2, pA2, pB2);

    float facA = rsqrtf(pA0 * pA0 + pA1 * pA1 + pA2 * pA2);
    float facB = rsqrtf(pB0 * pB0 + pB1 * pB1 + pB2 * pB2);

    // 6 consecutive floats starting at out + 6*(i/2); 8B-aligned -> 3x st.v2
    float2* o = (float2*)(out + 3 * i);
    o[0] = make_float2(pA0 * facA, pA1 * facA);
    o[1] = make_float2(pA2 * facA, pB0 * facB);
    o[2] = make_float2(pB1 * facB, pB2 * facB);
}

extern "C" void kernel_launch(void* const* d_in, const int* in_sizes, int n_in,
                              void* d_out, int out_size) {
    // 0:x 1:edge_index 2:edge_attr 3:u 4:batch
    // 5:w1a 6:b1a 7:w1b 8:b1b 9:w2a 10:b2a 11:w2b 12:b2b
    const float* x     = (const float*)d_in[0];
    const int*   ei    = (const int*)  d_in[1];
    const float* eattr = (const float*)d_in[2];
    const float* w1a   = (const float*)d_in[5];
    const float* b1a   = (const float*)d_in[6];
    const float* w1b   = (const float*)d_in[7];
    const float* b1b   = (const float*)d_in[8];
    const float* w2a   = (const float*)d_in[9];
    const float* b2a   = (const float*)d_in[10];
    const float* w2b   = (const float*)d_in[11];
    const float* b2b   = (const float*)d_in[12];
    float* out = (float*)d_out;

    prep_kernel<<<(N_NODES / 4) / 256, 256>>>((const float4*)x);
    edge_kernel<<<N_EDGES / 512, 256>>>(ei, eattr, w1a, b1a, w1b, b1b);
    node_kernel<<<N_NODES / 512, 256>>>(w2a, b2a, w2b, b2b, out);
}

// round 5
// speedup vs baseline: 1.0555x; 1.0555x over previous
#include <cuda_runtime.h>

#define N_NODES 1048576
#define N_EDGES (4 * N_NODES)

typedef unsigned long long u64;

// Scratch accumulator: per-node (sum0,sum1,sum2,count). 16 MB device global.
// Zero-initialized at module load; node_kernel re-zeros it after consuming,
// so every kernel_launch call sees a zeroed scratch.
__device__ float4 g_scr[N_NODES];

__device__ __forceinline__ u64 fma2(u64 a, u64 b, u64 c) {
    u64 d;
    asm("fma.rn.f32x2 %0, %1, %2, %3;" : "=l"(d) : "l"(a), "l"(b), "l"(c));
    return d;
}
__device__ __forceinline__ u64 pack2(float lo, float hi) {
    u64 d;
    asm("mov.b64 %0, {%1, %2};" : "=l"(d) : "f"(lo), "f"(hi));
    return d;
}
__device__ __forceinline__ void unpack2(u64 a, float& lo, float& hi) {
    asm("mov.b64 {%0, %1}, %2;" : "=f"(lo), "=f"(hi) : "l"(a));
}
__device__ __forceinline__ u64 relu2(u64 a) {
    float lo, hi;
    unpack2(a, lo, hi);
    return pack2(fmaxf(lo, 0.f), fmaxf(hi, 0.f));
}

// Edge MLP + scatter-add. TWO edges per thread, packed f32x2 math.
// Gathers x rows directly (12B rows, 3 scalar loads).
__global__ void __launch_bounds__(256) edge_kernel(
        const float* __restrict__ x,
        const int*   __restrict__ ei,
        const float* __restrict__ eattr,
        const float* __restrict__ w1a,
        const float* __restrict__ b1a,
        const float* __restrict__ w1b,
        const float* __restrict__ b1b) {
    // per hidden j: [wx, wy, wz, ww, bias, v0, v1, v2], each scalar duplicated.
    __shared__ __align__(16) u64 sw[20][8];
    int t = threadIdx.x;
    if (t < 20) {
        sw[t][0] = pack2(w1a[t],          w1a[t]);
        sw[t][1] = pack2(w1a[20 + t],     w1a[20 + t]);
        sw[t][2] = pack2(w1a[40 + t],     w1a[40 + t]);
        sw[t][3] = pack2(w1a[60 + t],     w1a[60 + t]);
        sw[t][4] = pack2(b1a[t],          b1a[t]);
        sw[t][5] = pack2(w1b[3 * t],      w1b[3 * t]);
        sw[t][6] = pack2(w1b[3 * t + 1],  w1b[3 * t + 1]);
        sw[t][7] = pack2(w1b[3 * t + 2],  w1b[3 * t + 2]);
    }
    __syncthreads();

    int e = (blockIdx.x * 256 + t) * 2;
    if (e >= N_EDGES) return;

    int2   rr = *(const int2*)(ei + e);             // source nodes
    int2   cc = *(const int2*)(ei + N_EDGES + e);   // destination nodes
    float2 ef = *(const float2*)(eattr + e);

    const float* xa = x + 3 * rr.x;
    const float* xb = x + 3 * rr.y;

    u64 X0 = pack2(__ldg(xa),     __ldg(xb));
    u64 X1 = pack2(__ldg(xa + 1), __ldg(xb + 1));
    u64 X2 = pack2(__ldg(xa + 2), __ldg(xb + 2));
    u64 EA = pack2(ef.x, ef.y);

    float bb0 = b1b[0], bb1 = b1b[1], bb2 = b1b[2];
    u64 o0 = pack2(bb0, bb0);
    u64 o1 = pack2(bb1, bb1);
    u64 o2 = pack2(bb2, bb2);

#pragma unroll
    for (int j = 0; j < 20; j++) {
        const u64* w = sw[j];
        u64 h = fma2(X0, w[0], fma2(X1, w[1], fma2(X2, w[2], fma2(EA, w[3], w[4]))));
        h = relu2(h);
        o0 = fma2(h, w[5], o0);
        o1 = fma2(h, w[6], o1);
        o2 = fma2(h, w[7], o2);
    }

    float a0, b0, a1, b1v, a2, b2v;
    unpack2(o0, a0, b0);
    unpack2(o1, a1, b1v);
    unpack2(o2, a2, b2v);

    asm volatile("red.global.add.v4.f32 [%0], {%1, %2, %3, %4};"
                 :: "l"(g_scr + cc.x), "f"(a0), "f"(a1), "f"(a2), "f"(1.0f) : "memory");
    asm volatile("red.global.add.v4.f32 [%0], {%1, %2, %3, %4};"
                 :: "l"(g_scr + cc.y), "f"(b0), "f"(b1v), "f"(b2v), "f"(1.0f) : "memory");
}

// Node MLP + L2 normalize + re-zero scratch. TWO nodes per thread.
__global__ void __launch_bounds__(256) node_kernel(
        const float* __restrict__ x,
        const float* __restrict__ w2a,
        const float* __restrict__ b2a,
        const float* __restrict__ w2b,
        const float* __restrict__ b2b,
        float* __restrict__ out) {
    // per hidden j: [w0..w5, bias, v0, v1, v2], duplicated. Row = 80B.
    __shared__ __align__(16) u64 sw[20][10];
    int t = threadIdx.x;
    if (t < 20) {
        sw[t][0] = pack2(w2a[t],           w2a[t]);
        sw[t][1] = pack2(w2a[20 + t],      w2a[20 + t]);
        sw[t][2] = pack2(w2a[40 + t],      w2a[40 + t]);
        sw[t][3] = pack2(w2a[60 + t],      w2a[60 + t]);
        sw[t][4] = pack2(w2a[80 + t],      w2a[80 + t]);
        sw[t][5] = pack2(w2a[100 + t],     w2a[100 + t]);
        sw[t][6] = pack2(b2a[t],           b2a[t]);
        sw[t][7] = pack2(w2b[3 * t],       w2b[3 * t]);
        sw[t][8] = pack2(w2b[3 * t + 1],   w2b[3 * t + 1]);
        sw[t][9] = pack2(w2b[3 * t + 2],   w2b[3 * t + 2]);
    }
    __syncthreads();

    int i = (blockIdx.x * 256 + t) * 2;
    if (i >= N_NODES) return;

    float4 sA = g_scr[i];
    float4 sB = g_scr[i + 1];
    // Re-zero scratch for the next call (deterministic across graph replays).
    float4 z = make_float4(0.f, 0.f, 0.f, 0.f);
    g_scr[i]     = z;
    g_scr[i + 1] = z;

    // x rows for nodes i, i+1: 6 consecutive floats, 8B-aligned (i even).
    const float2* px = (const float2*)(x + 3 * i);
    float2 xv0 = px[0];  // xA.x, xA.y
    float2 xv1 = px[1];  // xA.z, xB.x
    float2 xv2 = px[2];  // xB.y, xB.z

    float invA = 1.0f / fmaxf(sA.w, 1.0f);
    float invB = 1.0f / fmaxf(sB.w, 1.0f);

    u64 X0 = pack2(xv0.x, xv1.y);
    u64 X1 = pack2(xv0.y, xv2.x);
    u64 X2 = pack2(xv1.x, xv2.y);
    u64 A0 = pack2(sA.x * invA, sB.x * invB);
    u64 A1 = pack2(sA.y * invA, sB.y * invB);
    u64 A2 = pack2(sA.z * invA, sB.z * invB);

    float bb0 = b2b[0], bb1 = b2b[1], bb2 = b2b[2];
    u64 o0 = pack2(bb0, bb0);
    u64 o1 = pack2(bb1, bb1);
    u64 o2 = pack2(bb2, bb2);

#pragma unroll
    for (int j = 0; j < 20; j++) {
        const u64* w = sw[j];
        u64 h = fma2(X0, w[0],
                fma2(X1, w[1],
                fma2(X2, w[2],
                fma2(A0, w[3],
                fma2(A1, w[4],
                fma2(A2, w[5], w[6]))))));
        h = relu2(h);
        o0 = fma2(h, w[7], o0);
        o1 = fma2(h, w[8], o1);
        o2 = fma2(h, w[9], o2);
    }

    float pA0, pB0, pA1, pB1, pA2, pB2;
    unpack2(o0, pA0, pB0);
    unpack2(o1, pA1, pB1);
    unpack2(o2, pA2, pB2);

    float facA = rsqrtf(pA0 * pA0 + pA1 * pA1 + pA2 * pA2);
    float facB = rsqrtf(pB0 * pB0 + pB1 * pB1 + pB2 * pB2);

    // 6 consecutive floats, 8B-aligned -> 3x st.v2
    float2* o = (float2*)(out + 3 * i);
    o[0] = make_float2(pA0 * facA, pA1 * facA);
    o[1] = make_float2(pA2 * facA, pB0 * facB);
    o[2] = make_float2(pB1 * facB, pB2 * facB);
}

extern "C" void kernel_launch(void* const* d_in, const int* in_sizes, int n_in,
                              void* d_out, int out_size) {
    // 0:x 1:edge_index 2:edge_attr 3:u 4:batch
    // 5:w1a 6:b1a 7:w1b 8:b1b 9:w2a 10:b2a 11:w2b 12:b2b
    const float* x     = (const float*)d_in[0];
    const int*   ei    = (const int*)  d_in[1];
    const float* eattr = (const float*)d_in[2];
    const float* w1a   = (const float*)d_in[5];
    const float* b1a   = (const float*)d_in[6];
    const float* w1b   = (const float*)d_in[7];
    const float* b1b   = (const float*)d_in[8];
    const float* w2a   = (const float*)d_in[9];
    const float* b2a   = (const float*)d_in[10];
    const float* w2b   = (const float*)d_in[11];
    const float* b2b   = (const float*)d_in[12];
    float* out = (float*)d_out;

    edge_kernel<<<N_EDGES / 512, 256>>>(x, ei, eattr, w1a, b1a, w1b, b1b);
    node_kernel<<<N_NODES / 512, 256>>>(x, w2a, b2a, w2b, b2b, out);
}

// round 6
// speedup vs baseline: 1.2435x; 1.1781x over previous
#include <cuda_runtime.h>

#define N_NODES 1048576
#define N_EDGES (4 * N_NODES)

typedef unsigned long long u64;

// Scratch accumulator: per-node (sum0,sum1,sum2,count). 16 MB device global.
// Zero-initialized at module load; node_kernel re-zeros after consuming, so
// every kernel_launch call sees a zeroed scratch.
__device__ float4 g_scr[N_NODES];

__device__ __forceinline__ u64 fma2(u64 a, u64 b, u64 c) {
    u64 d;
    asm("fma.rn.f32x2 %0, %1, %2, %3;" : "=l"(d) : "l"(a), "l"(b), "l"(c));
    return d;
}
__device__ __forceinline__ u64 pack2(float lo, float hi) {
    u64 d;
    asm("mov.b64 %0, {%1, %2};" : "=l"(d) : "f"(lo), "f"(hi));
    return d;
}
__device__ __forceinline__ void unpack2(u64 a, float& lo, float& hi) {
    asm("mov.b64 {%0, %1}, %2;" : "=f"(lo), "=f"(hi) : "l"(a));
}
__device__ __forceinline__ u64 relu2(u64 a) {
    float lo, hi;
    unpack2(a, lo, hi);
    return pack2(fmaxf(lo, 0.f), fmaxf(hi, 0.f));
}

// Edge MLP + scatter-add. FOUR edges per thread, two packed f32x2 streams.
__global__ void __launch_bounds__(256) edge_kernel(
        const float* __restrict__ x,
        const int*   __restrict__ ei,
        const float* __restrict__ eattr,
        const float* __restrict__ w1a,
        const float* __restrict__ b1a,
        const float* __restrict__ w1b,
        const float* __restrict__ b1b) {
    // per hidden j: [wx, wy, wz, ww, bias, v0, v1, v2], each scalar duplicated.
    __shared__ __align__(16) u64 sw[20][8];
    int t = threadIdx.x;
    if (t < 20) {
        sw[t][0] = pack2(w1a[t],          w1a[t]);
        sw[t][1] = pack2(w1a[20 + t],     w1a[20 + t]);
        sw[t][2] = pack2(w1a[40 + t],     w1a[40 + t]);
        sw[t][3] = pack2(w1a[60 + t],     w1a[60 + t]);
        sw[t][4] = pack2(b1a[t],          b1a[t]);
        sw[t][5] = pack2(w1b[3 * t],      w1b[3 * t]);
        sw[t][6] = pack2(w1b[3 * t + 1],  w1b[3 * t + 1]);
        sw[t][7] = pack2(w1b[3 * t + 2],  w1b[3 * t + 2]);
    }
    __syncthreads();

    int e = (blockIdx.x * 256 + t) * 4;
    if (e >= N_EDGES) return;

    int4   rr = *(const int4*)(ei + e);             // source nodes A,B,C,D
    int4   cc = *(const int4*)(ei + N_EDGES + e);   // destination nodes
    float4 ef = *(const float4*)(eattr + e);

    const float* xa = x + 3 * rr.x;
    const float* xb = x + 3 * rr.y;
    const float* xc = x + 3 * rr.z;
    const float* xd = x + 3 * rr.w;

    // Issue all 12 gather loads up front (MLP ~12) to hide L2 latency.
    float a0 = __ldg(xa), a1 = __ldg(xa + 1), a2 = __ldg(xa + 2);
    float b0 = __ldg(xb), b1 = __ldg(xb + 1), b2 = __ldg(xb + 2);
    float c0 = __ldg(xc), c1 = __ldg(xc + 1), c2 = __ldg(xc + 2);
    float d0 = __ldg(xd), d1 = __ldg(xd + 1), d2 = __ldg(xd + 2);

    u64 X0ab = pack2(a0, b0), X0cd = pack2(c0, d0);
    u64 X1ab = pack2(a1, b1), X1cd = pack2(c1, d1);
    u64 X2ab = pack2(a2, b2), X2cd = pack2(c2, d2);
    u64 EAab = pack2(ef.x, ef.y), EAcd = pack2(ef.z, ef.w);

    float bb0 = b1b[0], bb1 = b1b[1], bb2 = b1b[2];
    u64 o0ab = pack2(bb0, bb0), o0cd = o0ab;
    u64 o1ab = pack2(bb1, bb1), o1cd = o1ab;
    u64 o2ab = pack2(bb2, bb2), o2cd = o2ab;

#pragma unroll
    for (int j = 0; j < 20; j++) {
        const u64* w = sw[j];
        u64 hab = fma2(X0ab, w[0], fma2(X1ab, w[1], fma2(X2ab, w[2], fma2(EAab, w[3], w[4]))));
        u64 hcd = fma2(X0cd, w[0], fma2(X1cd, w[1], fma2(X2cd, w[2], fma2(EAcd, w[3], w[4]))));
        hab = relu2(hab);
        hcd = relu2(hcd);
        o0ab = fma2(hab, w[5], o0ab);  o0cd = fma2(hcd, w[5], o0cd);
        o1ab = fma2(hab, w[6], o1ab);  o1cd = fma2(hcd, w[6], o1cd);
        o2ab = fma2(hab, w[7], o2ab);  o2cd = fma2(hcd, w[7], o2cd);
    }

    float pA0, pB0, pA1, pB1, pA2, pB2;
    float pC0, pD0, pC1, pD1, pC2, pD2;
    unpack2(o0ab, pA0, pB0); unpack2(o1ab, pA1, pB1); unpack2(o2ab, pA2, pB2);
    unpack2(o0cd, pC0, pD0); unpack2(o1cd, pC1, pD1); unpack2(o2cd, pC2, pD2);

    asm volatile("red.global.add.v4.f32 [%0], {%1, %2, %3, %4};"
                 :: "l"(g_scr + cc.x), "f"(pA0), "f"(pA1), "f"(pA2), "f"(1.0f) : "memory");
    asm volatile("red.global.add.v4.f32 [%0], {%1, %2, %3, %4};"
                 :: "l"(g_scr + cc.y), "f"(pB0), "f"(pB1), "f"(pB2), "f"(1.0f) : "memory");
    asm volatile("red.global.add.v4.f32 [%0], {%1, %2, %3, %4};"
                 :: "l"(g_scr + cc.z), "f"(pC0), "f"(pC1), "f"(pC2), "f"(1.0f) : "memory");
    asm volatile("red.global.add.v4.f32 [%0], {%1, %2, %3, %4};"
                 :: "l"(g_scr + cc.w), "f"(pD0), "f"(pD1), "f"(pD2), "f"(1.0f) : "memory");
}

// Node MLP + L2 normalize + re-zero scratch. FOUR nodes per thread.
__global__ void __launch_bounds__(256) node_kernel(
        const float* __restrict__ x,
        const float* __restrict__ w2a,
        const float* __restrict__ b2a,
        const float* __restrict__ w2b,
        const float* __restrict__ b2b,
        float* __restrict__ out) {
    // per hidden j: [w0..w5, bias, v0, v1, v2], duplicated. Row = 80B.
    __shared__ __align__(16) u64 sw[20][10];
    int t = threadIdx.x;
    if (t < 20) {
        sw[t][0] = pack2(w2a[t],           w2a[t]);
        sw[t][1] = pack2(w2a[20 + t],      w2a[20 + t]);
        sw[t][2] = pack2(w2a[40 + t],      w2a[40 + t]);
        sw[t][3] = pack2(w2a[60 + t],      w2a[60 + t]);
        sw[t][4] = pack2(w2a[80 + t],      w2a[80 + t]);
        sw[t][5] = pack2(w2a[100 + t],     w2a[100 + t]);
        sw[t][6] = pack2(b2a[t],           b2a[t]);
        sw[t][7] = pack2(w2b[3 * t],       w2b[3 * t]);
        sw[t][8] = pack2(w2b[3 * t + 1],   w2b[3 * t + 1]);
        sw[t][9] = pack2(w2b[3 * t + 2],   w2b[3 * t + 2]);
    }
    __syncthreads();

    int i = (blockIdx.x * 256 + t) * 4;
    if (i >= N_NODES) return;

    float4 sA = g_scr[i];
    float4 sB = g_scr[i + 1];
    float4 sC = g_scr[i + 2];
    float4 sD = g_scr[i + 3];
    // x rows for 4 nodes: 12 consecutive floats, 16B-aligned.
    const float4* px = (const float4*)(x + 3 * i);
    float4 xv0 = px[0];  // A.x A.y A.z B.x
    float4 xv1 = px[1];  // B.y B.z C.x C.y
    float4 xv2 = px[2];  // C.z D.x D.y D.z

    // Re-zero scratch for the next call.
    float4 z = make_float4(0.f, 0.f, 0.f, 0.f);
    g_scr[i]     = z;
    g_scr[i + 1] = z;
    g_scr[i + 2] = z;
    g_scr[i + 3] = z;

    float invA = 1.0f / fmaxf(sA.w, 1.0f);
    float invB = 1.0f / fmaxf(sB.w, 1.0f);
    float invC = 1.0f / fmaxf(sC.w, 1.0f);
    float invD = 1.0f / fmaxf(sD.w, 1.0f);

    u64 X0ab = pack2(xv0.x, xv0.w), X0cd = pack2(xv1.z, xv2.y);
    u64 X1ab = pack2(xv0.y, xv1.x), X1cd = pack2(xv1.w, xv2.z);
    u64 X2ab = pack2(xv0.z, xv1.y), X2cd = pack2(xv2.x, xv2.w);
    u64 A0ab = pack2(sA.x * invA, sB.x * invB), A0cd = pack2(sC.x * invC, sD.x * invD);
    u64 A1ab = pack2(sA.y * invA, sB.y * invB), A1cd = pack2(sC.y * invC, sD.y * invD);
    u64 A2ab = pack2(sA.z * invA, sB.z * invB), A2cd = pack2(sC.z * invC, sD.z * invD);

    float bb0 = b2b[0], bb1 = b2b[1], bb2 = b2b[2];
    u64 o0ab = pack2(bb0, bb0), o0cd = o0ab;
    u64 o1ab = pack2(bb1, bb1), o1cd = o1ab;
    u64 o2ab = pack2(bb2, bb2), o2cd = o2ab;

#pragma unroll
    for (int j = 0; j < 20; j++) {
        const u64* w = sw[j];
        u64 hab = fma2(X0ab, w[0],
                  fma2(X1ab, w[1],
                  fma2(X2ab, w[2],
                  fma2(A0ab, w[3],
                  fma2(A1ab, w[4],
                  fma2(A2ab, w[5], w[6]))))));
        u64 hcd = fma2(X0cd, w[0],
                  fma2(X1cd, w[1],
                  fma2(X2cd, w[2],
                  fma2(A0cd, w[3],
                  fma2(A1cd, w[4],
                  fma2(A2cd, w[5], w[6]))))));
        hab = relu2(hab);
        hcd = relu2(hcd);
        o0ab = fma2(hab, w[7], o0ab);  o0cd = fma2(hcd, w[7], o0cd);
        o1ab = fma2(hab, w[8], o1ab);  o1cd = fma2(hcd, w[8], o1cd);
        o2ab = fma2(hab, w[9], o2ab);  o2cd = fma2(hcd, w[9], o2cd);
    }

    float pA0, pB0, pA1, pB1, pA2, pB2;
    float pC0, pD0, pC1, pD1, pC2, pD2;
    unpack2(o0ab, pA0, pB0); unpack2(o1ab, pA1, pB1); unpack2(o2ab, pA2, pB2);
    unpack2(o0cd, pC0, pD0); unpack2(o1cd, pC1, pD1); unpack2(o2cd, pC2, pD2);

    float facA = rsqrtf(pA0 * pA0 + pA1 * pA1 + pA2 * pA2);
    float facB = rsqrtf(pB0 * pB0 + pB1 * pB1 + pB2 * pB2);
    float facC = rsqrtf(pC0 * pC0 + pC1 * pC1 + pC2 * pC2);
    float facD = rsqrtf(pD0 * pD0 + pD1 * pD1 + pD2 * pD2);

    // 12 consecutive floats, 16B-aligned -> 3x STG.128
    float4* o = (float4*)(out + 3 * i);
    o[0] = make_float4(pA0 * facA, pA1 * facA, pA2 * facA, pB0 * facB);
    o[1] = make_float4(pB1 * facB, pB2 * facB, pC0 * facC, pC1 * facC);
    o[2] = make_float4(pC2 * facC, pD0 * facD, pD1 * facD, pD2 * facD);
}

extern "C" void kernel_launch(void* const* d_in, const int* in_sizes, int n_in,
                              void* d_out, int out_size) {
    // 0:x 1:edge_index 2:edge_attr 3:u 4:batch
    // 5:w1a 6:b1a 7:w1b 8:b1b 9:w2a 10:b2a 11:w2b 12:b2b
    const float* x     = (const float*)d_in[0];
    const int*   ei    = (const int*)  d_in[1];
    const float* eattr = (const float*)d_in[2];
    const float* w1a   = (const float*)d_in[5];
    const float* b1a   = (const float*)d_in[6];
    const float* w1b   = (const float*)d_in[7];
    const float* b1b   = (const float*)d_in[8];
    const float* w2a   = (const float*)d_in[9];
    const float* b2a   = (const float*)d_in[10];
    const float* w2b   = (const float*)d_in[11];
    const float* b2b   = (const float*)d_in[12];
    float* out = (float*)d_out;

    edge_kernel<<<N_EDGES / 1024, 256>>>(x, ei, eattr, w1a, b1a, w1b, b1b);
    node_kernel<<<N_NODES / 1024, 256>>>(x, w2a, b2a, w2b, b2b, out);
}